// round 14
// baseline (speedup 1.0000x reference)
#include <cuda_runtime.h>
#include <cuda_fp16.h>
#include <cstdint>
#include <math.h>

#define DI __device__ __forceinline__

// ---------------- problem sizes ----------------
#define IN_F   4096
#define OUT_F  4096
#define N_TOK  8192
#define NF     16

// ---------------- GEMM tiling ----------------
#define BM 128
#define BN 128
#define BK 64                        // fp16 per K chunk = 128 bytes/row
#define KCHUNKS (IN_F / BK)          // 64
#define TILEB (128 * 128)            // one 128x(64 fp16) tile = 16 KB
#define STAGEB (2 * TILEB)           // x, W = 32 KB
#define STAGES 3
#define SMEM_BYTES (STAGES * STAGEB) // 96 KB -> 2 CTAs/SM

// ---------------- production tasks ----------------
#define NTASK_W 1024                 // W tile tasks: 64 o-rows x 256 i-cols
#define NTASK_X 4096                 // x cvt tasks: 2 rows each
#define NTASK   (NTASK_W + NTASK_X)  // 5120
// smem overlay during production (inside the 96KB dynamic region)
#define SS_FLOATS (NF * 64)          // 1024 floats
#define CS_FLOATS (NF * 256)         // 4096 floats
#define STASK_OFF ((SS_FLOATS + CS_FLOATS) * 4)   // 20480

// ---------------- device scratch ----------------
__device__ __half g_xf[(size_t)N_TOK * IN_F];      // x in fp16
__device__ __half g_Wf[(size_t)OUT_F * IN_F];      // W in fp16
__device__ int g_ctr;                              // task queue counter
__device__ int g_xflag[N_TOK / BM];                // 64 groups, target 64
__device__ int g_wflag[OUT_F / BN];                // 32 groups, target 32

// ---------------- PTX helpers (plain sm_103-safe subset) ----------------
DI uint32_t smem_to_u32(const void* p) {
    uint32_t a;
    asm("{ .reg .u64 t; cvta.to.shared.u64 t, %1; cvt.u32.u64 %0, t; }" : "=r"(a) : "l"(p));
    return a;
}

DI uint32_t sw128(uint32_t off) { return off ^ ((off >> 3) & 0x70); }

DI void cp16(uint32_t s, const void* g) {
    asm volatile("cp.async.cg.shared.global [%0], [%1], 16;" :: "r"(s), "l"(g));
}
#define CP_COMMIT() asm volatile("cp.async.commit_group;" ::: "memory")
#define CP_WAIT1()  asm volatile("cp.async.wait_group 1;" ::: "memory")

DI void ldsm4(uint32_t* r, uint32_t addr) {
    asm volatile("ldmatrix.sync.aligned.m8n8.x4.shared.b16 {%0,%1,%2,%3}, [%4];"
                 : "=r"(r[0]), "=r"(r[1]), "=r"(r[2]), "=r"(r[3]) : "r"(addr));
}

DI void mma_fp16(float* c, const uint32_t* a, const uint32_t* b) {
    asm volatile(
        "mma.sync.aligned.m16n8k16.row.col.f32.f16.f16.f32 "
        "{%0,%1,%2,%3}, {%4,%5,%6,%7}, {%8,%9}, {%0,%1,%2,%3};"
        : "+f"(c[0]), "+f"(c[1]), "+f"(c[2]), "+f"(c[3])
        : "r"(a[0]), "r"(a[1]), "r"(a[2]), "r"(a[3]), "r"(b[0]), "r"(b[1]));
}

// ---------------- small math helpers ----------------
DI float tanh_fast(float v) {
    float av = fabsf(v);
    float e;
    asm("ex2.approx.f32 %0, %1;" : "=f"(e) : "f"(av * 2.8853900817779268f)); // exp(2|v|)
    float r = 1.0f - __fdividef(2.0f, e + 1.0f);
    return copysignf(r, v);
}

// ---------------- reset kernel (flags/counter zeroed every call) ----------------
__global__ void k_reset() {
    const int t = threadIdx.x;
    if (t == 0) g_ctr = 0;
    if (t < N_TOK / BM)  g_xflag[t] = 0;
    if (t < OUT_F / BN)  g_wflag[t] = 0;
}

// ---------------- production tasks (run inside k_fused, 128 threads) ----------------
// x task: convert 2 rows (8192 fp32 -> fp16). Batched LDG.128 for MLP.
DI void do_task_x(int t, const float4* __restrict__ x, int tid) {
    const float4* src = x + (size_t)t * 2048;          // 2 rows * 1024 float4
    uint4* dst = ((uint4*)g_xf) + (size_t)t * 1024;    // 2 rows * 512 uint4
    #pragma unroll
    for (int h = 0; h < 2; ++h) {
        float4 v[8];
        const int base = h * 512 + tid;
        #pragma unroll
        for (int j = 0; j < 4; ++j) {
            v[2 * j]     = src[2 * (base + j * 128)];
            v[2 * j + 1] = src[2 * (base + j * 128) + 1];
        }
        #pragma unroll
        for (int j = 0; j < 4; ++j) {
            __half2 h0 = __floats2half2_rn(v[2 * j].x,     v[2 * j].y);
            __half2 h1 = __floats2half2_rn(v[2 * j].z,     v[2 * j].w);
            __half2 h2 = __floats2half2_rn(v[2 * j + 1].x, v[2 * j + 1].y);
            __half2 h3 = __floats2half2_rn(v[2 * j + 1].z, v[2 * j + 1].w);
            dst[base + j * 128] = make_uint4(*(uint32_t*)&h0, *(uint32_t*)&h1,
                                             *(uint32_t*)&h2, *(uint32_t*)&h3);
        }
    }
}

// W task: synthesize 64 o-rows x 256 i-cols of W (same math as before, MUFU).
DI void do_task_w(int w,
                  const float* __restrict__ amp, const float* __restrict__ rf,
                  const float* __restrict__ cf, const float* __restrict__ rp,
                  const float* __restrict__ cp,
                  const float* __restrict__ lora_A, const float* __restrict__ lora_B,
                  float as, float bs, float* Ss, float* Cs, int tid) {
    const int i0 = (w & 15) * 256;
    const int o0 = (w >> 4) * 64;
    const float TWO_PI = 6.28318530717958647692f;
    for (int t2 = tid; t2 < NF * 64; t2 += 128) {
        const int k = t2 >> 6, o = o0 + (t2 & 63);
        const float r = TWO_PI * ((float)o / (float)(OUT_F - 1));
        Ss[t2] = amp[k] * __sinf(fmaf(r, rf[k], rp[k]));
    }
    for (int t2 = tid; t2 < NF * 256; t2 += 128) {
        const int k = t2 >> 8, i = i0 + (t2 & 255);
        const float c = TWO_PI * ((float)i / (float)(IN_F - 1));
        Cs[t2] = __cosf(fmaf(c, cf[k], cp[k]));
    }
    __syncthreads();
    for (int g = tid; g < 64 * 64; g += 128) {
        const int r  = g >> 6;
        const int cg = g & 63;
        const int o  = o0 + r;
        const int i  = i0 + cg * 4;
        float4 acc = make_float4(0.f, 0.f, 0.f, 0.f);
        #pragma unroll
        for (int k = 0; k < NF; ++k) {
            float s = Ss[k * 64 + r];
            float4 c4 = *(const float4*)&Cs[k * 256 + cg * 4];
            acc.x = fmaf(s, c4.x, acc.x);
            acc.y = fmaf(s, c4.y, acc.y);
            acc.z = fmaf(s, c4.z, acc.z);
            acc.w = fmaf(s, c4.w, acc.w);
        }
        const float a0 = lora_A[o * 2 + 0], a1 = lora_A[o * 2 + 1];
        const float4 B0 = ((const float4*)lora_B)[i >> 2];
        const float4 B1 = ((const float4*)(lora_B + IN_F))[i >> 2];
        // tanh(W_lora) == W_lora to ~1e-12 abs (entries ~1e-4): linearized.
        float w0 = fmaf(as, tanh_fast(acc.x), bs * fmaf(a0, B0.x, a1 * B1.x));
        float w1 = fmaf(as, tanh_fast(acc.y), bs * fmaf(a0, B0.y, a1 * B1.y));
        float w2 = fmaf(as, tanh_fast(acc.z), bs * fmaf(a0, B0.z, a1 * B1.z));
        float w3 = fmaf(as, tanh_fast(acc.w), bs * fmaf(a0, B0.w, a1 * B1.w));
        __half2 h0 = __floats2half2_rn(w0, w1);
        __half2 h1 = __floats2half2_rn(w2, w3);
        size_t off = (size_t)o * IN_F + i;
        *(uint2*)(g_Wf + off) = make_uint2(*(uint32_t*)&h0, *(uint32_t*)&h1);
    }
}

DI void spin_flag(const int* f, int target) {
    volatile const int* vf = (volatile const int*)f;
    while (*vf < target) __nanosleep(200);
}

// ---------------- fused kernel: produce (work-stealing) then GEMM ----------------
// GEMM: 128 threads (4 warps, 2x2), warp tile 64x64 — mainloop identical to R13.
DI void stage_fill(uint32_t sbase, const __half* gx, const __half* gw, uint32_t s0) {
    #pragma unroll
    for (int r = 0; r < 8; ++r) {
        cp16(sbase + s0 + r * 2048,         gx + (size_t)(r * 16) * IN_F);
        cp16(sbase + s0 + r * 2048 + TILEB, gw + (size_t)(r * 16) * IN_F);
    }
}

__global__ void __launch_bounds__(128, 2) k_fused(
        const float* __restrict__ x,
        const float* __restrict__ amp, const float* __restrict__ rf,
        const float* __restrict__ cf, const float* __restrict__ rp,
        const float* __restrict__ cp,
        const float* __restrict__ lora_A, const float* __restrict__ lora_B,
        const float* __restrict__ alpha, const float* __restrict__ beta,
        const float* __restrict__ bias, float* __restrict__ out) {
    extern __shared__ char smem[];
    const uint32_t sb = smem_to_u32(smem);
    const int tid  = threadIdx.x;
    const int wid  = tid >> 5;
    const int lane = tid & 31;
    const int n0 = blockIdx.x * BN;
    const int m0 = blockIdx.y * BM;
    const int wm = wid & 1;                 // 0..1 -> 64-row slab of x
    const int wn = wid >> 1;                // 0..1 -> 64-col slab of W

    // ======== phase 1: drain production queue (work-stealing) ========
    {
        // std = sqrt(2/(in+out)) = 1/64 exactly
        const float as = (1.0f / (1.0f + __expf(-alpha[0]))) * 0.015625f;
        const float bs = (1.0f / (1.0f + __expf(-beta[0])))  * 0.015625f;
        float* Ss = (float*)smem;
        float* Cs = Ss + SS_FLOATS;
        volatile int* s_task = (volatile int*)(smem + STASK_OFF);
        while (true) {
            if (tid == 0) *s_task = atomicAdd(&g_ctr, 1);
            __syncthreads();
            const int t = *s_task;
            if (t >= NTASK) break;
            if (t % 5 == 0) {
                do_task_w(t / 5, amp, rf, cf, rp, cp, lora_A, lora_B,
                          as, bs, Ss, Cs, tid);
            } else {
                do_task_x(t - t / 5 - 1, (const float4*)x, tid);
            }
            __threadfence();
            __syncthreads();                 // all lanes' writes fenced; smem reusable
            if (tid == 0) {
                if (t % 5 == 0) atomicAdd(&g_wflag[(t / 5) >> 5], 1);
                else            atomicAdd(&g_xflag[(t - t / 5 - 1) >> 6], 1);
            }
        }
        // wait for this CTA's inputs (produced by resident CTAs -> no deadlock)
        spin_flag(&g_xflag[blockIdx.y], 64);
        spin_flag(&g_wflag[blockIdx.x], 32);
        __threadfence();
        __syncthreads();
    }

    // ======== phase 2: GEMM (identical to R13) ========
    float acc[4][8][4];
    #pragma unroll
    for (int i = 0; i < 4; ++i)
        #pragma unroll
        for (int j = 0; j < 8; ++j)
            #pragma unroll
            for (int q = 0; q < 4; ++q) acc[i][j][q] = 0.f;

    const __half* gx = g_xf + (size_t)(m0 + (tid >> 3)) * IN_F + (tid & 7) * 8;
    const __half* gw = g_Wf + (size_t)(n0 + (tid >> 3)) * IN_F + (tid & 7) * 8;
    const uint32_t s0 = sw128((uint32_t)((tid >> 3) * 128 + (tid & 7) * 16));

    uint32_t aoff[4], boff[4];
    {
        const int arow_l = (lane & 15);
        const int akb    = (lane >> 4) * 16;
        #pragma unroll
        for (int mi = 0; mi < 4; ++mi) {
            const int row = wm * 64 + mi * 16 + arow_l;
            aoff[mi] = sw128((uint32_t)(row * 128 + akb));
        }
        const int brow_l = (lane & 7) + ((lane >> 4) << 3);
        const int bkb    = ((lane >> 3) & 1) * 16;
        #pragma unroll
        for (int pi = 0; pi < 4; ++pi) {
            const int row = wn * 64 + pi * 16 + brow_l;
            boff[pi] = sw128((uint32_t)(row * 128 + bkb));
        }
    }

    // prologue: 2 stages in flight
    stage_fill(sb + 0 * STAGEB, gx, gw, s0);
    CP_COMMIT();
    gx += BK; gw += BK;
    stage_fill(sb + 1 * STAGEB, gx, gw, s0);
    CP_COMMIT();
    gx += BK; gw += BK;

    uint32_t st = sb;
    uint32_t fs = sb + 2 * STAGEB;
    const uint32_t send = sb + 3 * STAGEB;

    uint32_t ah[2][4][4], bh[2][8][2];

    CP_WAIT1();
    __syncthreads();
    #pragma unroll
    for (int mi = 0; mi < 4; ++mi)
        ldsm4(ah[0][mi], st + aoff[mi]);
    #pragma unroll
    for (int pi = 0; pi < 4; ++pi)
        ldsm4(&bh[0][2 * pi][0], st + TILEB + boff[pi]);

    for (int it = 0; it < KCHUNKS; ++it) {
        if (it + 2 < KCHUNKS) {
            stage_fill(fs, gx, gw, s0);
            gx += BK; gw += BK;
            fs += STAGEB; if (fs == send) fs = sb;
        }
        CP_COMMIT();

        #pragma unroll
        for (int ks = 0; ks < 3; ++ks) {
            const int cur = ks & 1, nxt = cur ^ 1;
            const uint32_t kb = (uint32_t)((ks + 1) * 32);   // kb<128: sw128(kb)==kb
            #pragma unroll
            for (int mi = 0; mi < 4; ++mi)
                ldsm4(ah[nxt][mi], st + (aoff[mi] ^ kb));
            #pragma unroll
            for (int pi = 0; pi < 4; ++pi)
                ldsm4(&bh[nxt][2 * pi][0], st + TILEB + (boff[pi] ^ kb));
            #pragma unroll
            for (int mi = 0; mi < 4; ++mi)
                #pragma unroll
                for (int ni = 0; ni < 8; ++ni)
                    mma_fp16(acc[mi][ni], ah[cur][mi], bh[cur][ni]);
        }

        CP_WAIT1();
        __syncthreads();

        {
            const uint32_t stn = (st + STAGEB == send) ? sb : st + STAGEB;
            #pragma unroll
            for (int mi = 0; mi < 4; ++mi)
                ldsm4(ah[0][mi], stn + aoff[mi]);
            #pragma unroll
            for (int pi = 0; pi < 4; ++pi)
                ldsm4(&bh[0][2 * pi][0], stn + TILEB + boff[pi]);
            #pragma unroll
            for (int mi = 0; mi < 4; ++mi)
                #pragma unroll
                for (int ni = 0; ni < 8; ++ni)
                    mma_fp16(acc[mi][ni], ah[1][mi], bh[1][ni]);
            st = stn;
        }
    }

    // epilogue: acc -> out (+bias)
    const int gid = lane >> 2, tig = lane & 3;
    const int mbase = m0 + wm * 64;
    const int nbase = n0 + wn * 64;
    #pragma unroll
    for (int ni = 0; ni < 8; ++ni) {
        const int n = nbase + ni * 8 + 2 * tig;
        const float2 bv = *(const float2*)(bias + n);
        #pragma unroll
        for (int mi = 0; mi < 4; ++mi) {
            const int m = mbase + mi * 16 + gid;
            float2 v0, v1;
            v0.x = acc[mi][ni][0] + bv.x;  v0.y = acc[mi][ni][1] + bv.y;
            v1.x = acc[mi][ni][2] + bv.x;  v1.y = acc[mi][ni][3] + bv.y;
            *(float2*)(out + (size_t)m * OUT_F + n)       = v0;
            *(float2*)(out + (size_t)(m + 8) * OUT_F + n) = v1;
        }
    }
}

// ---------------- launch ----------------
extern "C" void kernel_launch(void* const* d_in, const int* in_sizes, int n_in,
                              void* d_out, int out_size) {
    const float* x      = (const float*)d_in[0];
    const float* amp    = (const float*)d_in[1];
    const float* rf     = (const float*)d_in[2];
    const float* cf     = (const float*)d_in[3];
    const float* rp     = (const float*)d_in[4];
    const float* cp     = (const float*)d_in[5];
    const float* lora_A = (const float*)d_in[6];
    const float* lora_B = (const float*)d_in[7];
    const float* alpha  = (const float*)d_in[8];
    const float* beta   = (const float*)d_in[9];
    const float* bias   = (const float*)d_in[10];
    float* out = (float*)d_out;

    cudaFuncSetAttribute(k_fused, cudaFuncAttributeMaxDynamicSharedMemorySize, SMEM_BYTES);

    k_reset<<<1, 128>>>();
    k_fused<<<dim3(OUT_F / BN, N_TOK / BM), 128, SMEM_BYTES>>>(
        x, amp, rf, cf, rp, cp, lora_A, lora_B, alpha, beta, bias, out);
}

// round 15
// speedup vs baseline: 1.0177x; 1.0177x over previous
#include <cuda_runtime.h>
#include <cuda_fp16.h>
#include <cstdint>
#include <math.h>

#define DI __device__ __forceinline__

// ---------------- problem sizes ----------------
#define IN_F   4096
#define OUT_F  4096
#define N_TOK  8192
#define NF     16

// ---------------- GEMM tiling ----------------
#define BM 128
#define BN 128
#define BK 64                        // fp16 per K chunk = 128 bytes/row
#define KCHUNKS (IN_F / BK)          // 64
#define TILEB (128 * 128)            // one 128x(64 fp16) tile = 16 KB
#define STAGEB (2 * TILEB)           // x, W = 32 KB
#define STAGES 3
#define SMEM_BYTES (STAGES * STAGEB) // 96 KB -> 2 CTAs/SM

// ---------------- device scratch ----------------
__device__ __half g_xf[(size_t)N_TOK * IN_F];      // x in fp16
__device__ __half g_Wf[(size_t)OUT_F * IN_F];      // W in fp16

// ---------------- PTX helpers (plain sm_103-safe subset) ----------------
DI uint32_t smem_to_u32(const void* p) {
    uint32_t a;
    asm("{ .reg .u64 t; cvta.to.shared.u64 t, %1; cvt.u32.u64 %0, t; }" : "=r"(a) : "l"(p));
    return a;
}

DI uint32_t sw128(uint32_t off) { return off ^ ((off >> 3) & 0x70); }

DI void cp16(uint32_t s, const void* g) {
    asm volatile("cp.async.cg.shared.global [%0], [%1], 16;" :: "r"(s), "l"(g));
}
#define CP_COMMIT() asm volatile("cp.async.commit_group;" ::: "memory")
#define CP_WAIT1()  asm volatile("cp.async.wait_group 1;" ::: "memory")

DI void ldsm4(uint32_t* r, uint32_t addr) {
    asm volatile("ldmatrix.sync.aligned.m8n8.x4.shared.b16 {%0,%1,%2,%3}, [%4];"
                 : "=r"(r[0]), "=r"(r[1]), "=r"(r[2]), "=r"(r[3]) : "r"(addr));
}

DI void mma_fp16(float* c, const uint32_t* a, const uint32_t* b) {
    asm volatile(
        "mma.sync.aligned.m16n8k16.row.col.f32.f16.f16.f32 "
        "{%0,%1,%2,%3}, {%4,%5,%6,%7}, {%8,%9}, {%0,%1,%2,%3};"
        : "+f"(c[0]), "+f"(c[1]), "+f"(c[2]), "+f"(c[3])
        : "r"(a[0]), "r"(a[1]), "r"(a[2]), "r"(a[3]), "r"(b[0]), "r"(b[1]));
}

// ---------------- small math helpers ----------------
DI float tanh_fast(float v) {
    float av = fabsf(v);
    float e;
    asm("ex2.approx.f32 %0, %1;" : "=f"(e) : "f"(av * 2.8853900817779268f)); // exp(2|v|)
    float r = 1.0f - __fdividef(2.0f, e + 1.0f);
    return copysignf(r, v);
}

// ---------------- kernel 1: convert x to fp16 (16 floats/thread) ----------------
__global__ void k_cvt_x(const float4* __restrict__ x) {
    size_t idx = (size_t)blockIdx.x * 256 + threadIdx.x;
    float4 v[4];
    #pragma unroll
    for (int j = 0; j < 4; ++j) v[j] = x[4 * idx + j];     // 4x LDG.128 in flight
    uint4 o0, o1;
    {
        __half2 h0 = __floats2half2_rn(v[0].x, v[0].y);
        __half2 h1 = __floats2half2_rn(v[0].z, v[0].w);
        __half2 h2 = __floats2half2_rn(v[1].x, v[1].y);
        __half2 h3 = __floats2half2_rn(v[1].z, v[1].w);
        o0 = make_uint4(*(uint32_t*)&h0, *(uint32_t*)&h1,
                        *(uint32_t*)&h2, *(uint32_t*)&h3);
    }
    {
        __half2 h0 = __floats2half2_rn(v[2].x, v[2].y);
        __half2 h1 = __floats2half2_rn(v[2].z, v[2].w);
        __half2 h2 = __floats2half2_rn(v[3].x, v[3].y);
        __half2 h3 = __floats2half2_rn(v[3].z, v[3].w);
        o1 = make_uint4(*(uint32_t*)&h0, *(uint32_t*)&h1,
                        *(uint32_t*)&h2, *(uint32_t*)&h3);
    }
    ((uint4*)g_xf)[2 * idx]     = o0;
    ((uint4*)g_xf)[2 * idx + 1] = o1;
}

// ---------------- kernel 2: synthesize W (fourier tanh + linearized lora) ----------------
// 2 o-tiles (128 o-rows) per block: the NF x 256 cos table is built once and
// amortized over twice the output work.
__global__ void __launch_bounds__(256) k_build_w(
        const float* __restrict__ amp, const float* __restrict__ rf,
        const float* __restrict__ cf, const float* __restrict__ rp,
        const float* __restrict__ cp,
        const float* __restrict__ lora_A, const float* __restrict__ lora_B,
        const float* __restrict__ alpha, const float* __restrict__ beta) {
    __shared__ float Ss[NF][128];
    __shared__ float Cs[NF][256];
    const int tid = threadIdx.x;
    const int i0 = blockIdx.x * 256;
    const int o0 = blockIdx.y * 128;
    const float TWO_PI = 6.28318530717958647692f;
    // MUFU sin/cos: args are O(30), abs err ~1e-5 -> ~2e-5 on W, far below
    // the fp16 quantization (2.9e-4) that dominates rel_err.
    for (int t = tid; t < NF * 128; t += 256) {
        const int k = t >> 7, o = o0 + (t & 127);
        const float r = TWO_PI * ((float)o / (float)(OUT_F - 1));
        Ss[k][t & 127] = amp[k] * __sinf(fmaf(r, rf[k], rp[k]));
    }
    for (int t = tid; t < NF * 256; t += 256) {
        const int k = t >> 8, i = i0 + (t & 255);
        const float c = TWO_PI * ((float)i / (float)(IN_F - 1));
        Cs[k][t & 255] = __cosf(fmaf(c, cf[k], cp[k]));
    }
    __syncthreads();

    // std = sqrt(2/(in+out)) = sqrt(1/4096) = 1/64 exactly
    const float as = (1.0f / (1.0f + __expf(-alpha[0]))) * 0.015625f;
    const float bs = (1.0f / (1.0f + __expf(-beta[0])))  * 0.015625f;

    for (int g = tid; g < 128 * 64; g += 256) {
        const int r  = g >> 6;
        const int cg = g & 63;
        const int o  = o0 + r;
        const int i  = i0 + cg * 4;
        float4 acc = make_float4(0.f, 0.f, 0.f, 0.f);
        #pragma unroll
        for (int k = 0; k < NF; ++k) {
            float s = Ss[k][r];
            float4 c4 = *(const float4*)&Cs[k][cg * 4];
            acc.x = fmaf(s, c4.x, acc.x);
            acc.y = fmaf(s, c4.y, acc.y);
            acc.z = fmaf(s, c4.z, acc.z);
            acc.w = fmaf(s, c4.w, acc.w);
        }
        const float a0 = lora_A[o * 2 + 0], a1 = lora_A[o * 2 + 1];
        const float4 B0 = ((const float4*)lora_B)[i >> 2];
        const float4 B1 = ((const float4*)(lora_B + IN_F))[i >> 2];
        // tanh(W_lora) == W_lora to ~1e-12 abs (entries ~1e-4): linearized.
        float w0 = fmaf(as, tanh_fast(acc.x), bs * fmaf(a0, B0.x, a1 * B1.x));
        float w1 = fmaf(as, tanh_fast(acc.y), bs * fmaf(a0, B0.y, a1 * B1.y));
        float w2 = fmaf(as, tanh_fast(acc.z), bs * fmaf(a0, B0.z, a1 * B1.z));
        float w3 = fmaf(as, tanh_fast(acc.w), bs * fmaf(a0, B0.w, a1 * B1.w));
        __half2 h0 = __floats2half2_rn(w0, w1);
        __half2 h1 = __floats2half2_rn(w2, w3);
        size_t off = (size_t)o * IN_F + i;
        *(uint2*)(g_Wf + off) = make_uint2(*(uint32_t*)&h0, *(uint32_t*)&h1);
    }
}

// ---------------- kernel 3: mma.sync fp16 GEMM  out = x @ W^T + bias ----------------
// (byte-identical mainloop to R13: 128 threads, 2x2 warps, 64x64 warp tile,
// fragments prefetched one ks-step ahead incl. across chunk boundaries,
// ONE barrier per iteration.)
// smem stage layout: [x 16K][W 16K]; rows are 128B, SW128 swizzled.
DI void stage_fill(uint32_t sbase, const __half* gx, const __half* gw, uint32_t s0) {
    #pragma unroll
    for (int r = 0; r < 8; ++r) {
        cp16(sbase + s0 + r * 2048,         gx + (size_t)(r * 16) * IN_F);
        cp16(sbase + s0 + r * 2048 + TILEB, gw + (size_t)(r * 16) * IN_F);
    }
}

__global__ void __launch_bounds__(128, 2) k_gemm(const float* __restrict__ bias,
                                                 float* __restrict__ out) {
    extern __shared__ char smem[];
    const uint32_t sb = smem_to_u32(smem);
    const int tid  = threadIdx.x;
    const int wid  = tid >> 5;
    const int lane = tid & 31;
    const int n0 = blockIdx.x * BN;
    const int m0 = blockIdx.y * BM;
    const int wm = wid & 1;                 // 0..1 -> 64-row slab of x
    const int wn = wid >> 1;                // 0..1 -> 64-col slab of W

    float acc[4][8][4];
    #pragma unroll
    for (int i = 0; i < 4; ++i)
        #pragma unroll
        for (int j = 0; j < 8; ++j)
            #pragma unroll
            for (int q = 0; q < 4; ++q) acc[i][j][q] = 0.f;

    // persistent global pointers for the fill path
    const __half* gx = g_xf + (size_t)(m0 + (tid >> 3)) * IN_F + (tid & 7) * 8;
    const __half* gw = g_Wf + (size_t)(n0 + (tid >> 3)) * IN_F + (tid & 7) * 8;
    const uint32_t s0 = sw128((uint32_t)((tid >> 3) * 128 + (tid & 7) * 16));

    // precomputed ldmatrix smem offsets (stage-relative)
    uint32_t aoff[4], boff[4];
    {
        const int arow_l = (lane & 15);
        const int akb    = (lane >> 4) * 16;
        #pragma unroll
        for (int mi = 0; mi < 4; ++mi) {
            const int row = wm * 64 + mi * 16 + arow_l;
            aoff[mi] = sw128((uint32_t)(row * 128 + akb));
        }
        const int brow_l = (lane & 7) + ((lane >> 4) << 3);
        const int bkb    = ((lane >> 3) & 1) * 16;
        #pragma unroll
        for (int pi = 0; pi < 4; ++pi) {
            const int row = wn * 64 + pi * 16 + brow_l;
            boff[pi] = sw128((uint32_t)(row * 128 + bkb));
        }
    }

    // prologue: 2 stages in flight
    stage_fill(sb + 0 * STAGEB, gx, gw, s0);
    CP_COMMIT();
    gx += BK; gw += BK;
    stage_fill(sb + 1 * STAGEB, gx, gw, s0);
    CP_COMMIT();
    gx += BK; gw += BK;

    uint32_t st = sb;                        // compute stage base (cycles over 3)
    uint32_t fs = sb + 2 * STAGEB;           // fill stage base (cycles over 3)
    const uint32_t send = sb + 3 * STAGEB;

    uint32_t ah[2][4][4], bh[2][8][2];       // double-buffered fragments

    // make stage0 visible, preload its ks=0 fragments into buffer 0
    CP_WAIT1();
    __syncthreads();
    #pragma unroll
    for (int mi = 0; mi < 4; ++mi)
        ldsm4(ah[0][mi], st + aoff[mi]);
    #pragma unroll
    for (int pi = 0; pi < 4; ++pi)
        ldsm4(&bh[0][2 * pi][0], st + TILEB + boff[pi]);

    for (int it = 0; it < KCHUNKS; ++it) {
        // fill stage it+2 into slot (it+2)%3 == (it-1)%3 — safe: all reads of
        // that slot finished before the barrier of iteration it-1
        if (it + 2 < KCHUNKS) {
            stage_fill(fs, gx, gw, s0);
            gx += BK; gw += BK;
            fs += STAGEB; if (fs == send) fs = sb;
        }
        CP_COMMIT();

        // ks = 0..2: prefetch ks+1 (same stage), mma current
        #pragma unroll
        for (int ks = 0; ks < 3; ++ks) {
            const int cur = ks & 1, nxt = cur ^ 1;
            const uint32_t kb = (uint32_t)((ks + 1) * 32);   // kb<128: sw128(kb)==kb
            #pragma unroll
            for (int mi = 0; mi < 4; ++mi)
                ldsm4(ah[nxt][mi], st + (aoff[mi] ^ kb));
            #pragma unroll
            for (int pi = 0; pi < 4; ++pi)
                ldsm4(&bh[nxt][2 * pi][0], st + TILEB + (boff[pi] ^ kb));
            #pragma unroll
            for (int mi = 0; mi < 4; ++mi)
                #pragma unroll
                for (int ni = 0; ni < 8; ++ni)
                    mma_fp16(acc[mi][ni], ah[cur][mi], bh[cur][ni]);
        }

        CP_WAIT1();                           // retires fill of stage it+1
        __syncthreads();                      // stage it+1 visible; all reads of stage it done

        // ks = 3: prefetch ks0 of the NEXT stage into buf0, mma buf1
        {
            const uint32_t stn = (st + STAGEB == send) ? sb : st + STAGEB;
            #pragma unroll
            for (int mi = 0; mi < 4; ++mi)
                ldsm4(ah[0][mi], stn + aoff[mi]);
            #pragma unroll
            for (int pi = 0; pi < 4; ++pi)
                ldsm4(&bh[0][2 * pi][0], stn + TILEB + boff[pi]);
            #pragma unroll
            for (int mi = 0; mi < 4; ++mi)
                #pragma unroll
                for (int ni = 0; ni < 8; ++ni)
                    mma_fp16(acc[mi][ni], ah[1][mi], bh[1][ni]);
            st = stn;
        }
    }

    // epilogue: acc -> out (+bias)
    const int gid = lane >> 2, tig = lane & 3;
    const int mbase = m0 + wm * 64;
    const int nbase = n0 + wn * 64;
    #pragma unroll
    for (int ni = 0; ni < 8; ++ni) {
        const int n = nbase + ni * 8 + 2 * tig;
        const float2 bv = *(const float2*)(bias + n);
        #pragma unroll
        for (int mi = 0; mi < 4; ++mi) {
            const int m = mbase + mi * 16 + gid;
            float2 v0, v1;
            v0.x = acc[mi][ni][0] + bv.x;  v0.y = acc[mi][ni][1] + bv.y;
            v1.x = acc[mi][ni][2] + bv.x;  v1.y = acc[mi][ni][3] + bv.y;
            *(float2*)(out + (size_t)m * OUT_F + n)       = v0;
            *(float2*)(out + (size_t)(m + 8) * OUT_F + n) = v1;
        }
    }
}

// ---------------- launch ----------------
extern "C" void kernel_launch(void* const* d_in, const int* in_sizes, int n_in,
                              void* d_out, int out_size) {
    const float* x      = (const float*)d_in[0];
    const float* amp    = (const float*)d_in[1];
    const float* rf     = (const float*)d_in[2];
    const float* cf     = (const float*)d_in[3];
    const float* rp     = (const float*)d_in[4];
    const float* cp     = (const float*)d_in[5];
    const float* lora_A = (const float*)d_in[6];
    const float* lora_B = (const float*)d_in[7];
    const float* alpha  = (const float*)d_in[8];
    const float* beta   = (const float*)d_in[9];
    const float* bias   = (const float*)d_in[10];
    float* out = (float*)d_out;

    cudaFuncSetAttribute(k_gemm, cudaFuncAttributeMaxDynamicSharedMemorySize, SMEM_BYTES);

    k_cvt_x<<<((size_t)N_TOK * IN_F / 16) / 256, 256>>>((const float4*)x);
    k_build_w<<<dim3(IN_F / 256, OUT_F / 128), 256>>>(amp, rf, cf, rp, cp,
                                                      lora_A, lora_B, alpha, beta);
    k_gemm<<<dim3(OUT_F / BN, N_TOK / BM), 128, SMEM_BYTES>>>(bias, out);
}

// round 16
// speedup vs baseline: 1.0195x; 1.0017x over previous
#include <cuda_runtime.h>
#include <cuda_fp16.h>
#include <cstdint>
#include <math.h>

#define DI __device__ __forceinline__

// ---------------- problem sizes ----------------
#define IN_F   4096
#define OUT_F  4096
#define N_TOK  8192
#define NF     16

// ---------------- GEMM tiling ----------------
#define BM 128
#define BN 128
#define BK 64                        // fp16 per K chunk = 128 bytes/row
#define KCHUNKS (IN_F / BK)          // 64
#define TILEB (128 * 128)            // one 128x(64 fp16) tile = 16 KB
#define STAGEB (2 * TILEB)           // x, W = 32 KB
#define STAGES 3
#define SMEM_BYTES (STAGES * STAGEB) // 96 KB -> 2 CTAs/SM

// ---------------- device scratch ----------------
__device__ __half g_xf[(size_t)N_TOK * IN_F];      // x in fp16
__device__ __half g_Wf[(size_t)OUT_F * IN_F];      // W in fp16

// ---------------- PTX helpers (plain sm_103-safe subset) ----------------
DI uint32_t smem_to_u32(const void* p) {
    uint32_t a;
    asm("{ .reg .u64 t; cvta.to.shared.u64 t, %1; cvt.u32.u64 %0, t; }" : "=r"(a) : "l"(p));
    return a;
}

DI uint32_t sw128(uint32_t off) { return off ^ ((off >> 3) & 0x70); }

DI void cp16(uint32_t s, const void* g) {
    asm volatile("cp.async.cg.shared.global [%0], [%1], 16;" :: "r"(s), "l"(g));
}
#define CP_COMMIT() asm volatile("cp.async.commit_group;" ::: "memory")
#define CP_WAIT1()  asm volatile("cp.async.wait_group 1;" ::: "memory")

DI void ldsm4(uint32_t* r, uint32_t addr) {
    asm volatile("ldmatrix.sync.aligned.m8n8.x4.shared.b16 {%0,%1,%2,%3}, [%4];"
                 : "=r"(r[0]), "=r"(r[1]), "=r"(r[2]), "=r"(r[3]) : "r"(addr));
}

DI void mma_fp16(float* c, const uint32_t* a, const uint32_t* b) {
    asm volatile(
        "mma.sync.aligned.m16n8k16.row.col.f32.f16.f16.f32 "
        "{%0,%1,%2,%3}, {%4,%5,%6,%7}, {%8,%9}, {%0,%1,%2,%3};"
        : "+f"(c[0]), "+f"(c[1]), "+f"(c[2]), "+f"(c[3])
        : "r"(a[0]), "r"(a[1]), "r"(a[2]), "r"(a[3]), "r"(b[0]), "r"(b[1]));
}

// ---------------- small math helpers ----------------
DI float tanh_fast(float v) {
    float av = fabsf(v);
    float e;
    asm("ex2.approx.f32 %0, %1;" : "=f"(e) : "f"(av * 2.8853900817779268f)); // exp(2|v|)
    float r = 1.0f - __fdividef(2.0f, e + 1.0f);
    return copysignf(r, v);
}

// ---------------- kernel 1: convert x to fp16 (8 floats/thread, R12 form) ----------------
__global__ void k_cvt_x(const float4* __restrict__ x) {
    size_t idx = (size_t)blockIdx.x * 256 + threadIdx.x;
    float4 v0 = x[2 * idx];
    float4 v1 = x[2 * idx + 1];
    __half2 h0 = __floats2half2_rn(v0.x, v0.y);
    __half2 h1 = __floats2half2_rn(v0.z, v0.w);
    __half2 h2 = __floats2half2_rn(v1.x, v1.y);
    __half2 h3 = __floats2half2_rn(v1.z, v1.w);
    ((uint4*)g_xf)[idx] = make_uint4(*(uint32_t*)&h0, *(uint32_t*)&h1,
                                     *(uint32_t*)&h2, *(uint32_t*)&h3);
}

// ---------------- kernel 2: synthesize W (fourier tanh + linearized lora) ----------------
// 2 o-tiles (128 o-rows) per block: the NF x 256 cos table is built once and
// amortized over twice the output work.
__global__ void __launch_bounds__(256) k_build_w(
        const float* __restrict__ amp, const float* __restrict__ rf,
        const float* __restrict__ cf, const float* __restrict__ rp,
        const float* __restrict__ cp,
        const float* __restrict__ lora_A, const float* __restrict__ lora_B,
        const float* __restrict__ alpha, const float* __restrict__ beta) {
    __shared__ float Ss[NF][128];
    __shared__ float Cs[NF][256];
    const int tid = threadIdx.x;
    const int i0 = blockIdx.x * 256;
    const int o0 = blockIdx.y * 128;
    const float TWO_PI = 6.28318530717958647692f;
    // MUFU sin/cos: args are O(30), abs err ~1e-5 -> ~2e-5 on W, far below
    // the fp16 quantization (2.9e-4) that dominates rel_err.
    for (int t = tid; t < NF * 128; t += 256) {
        const int k = t >> 7, o = o0 + (t & 127);
        const float r = TWO_PI * ((float)o / (float)(OUT_F - 1));
        Ss[k][t & 127] = amp[k] * __sinf(fmaf(r, rf[k], rp[k]));
    }
    for (int t = tid; t < NF * 256; t += 256) {
        const int k = t >> 8, i = i0 + (t & 255);
        const float c = TWO_PI * ((float)i / (float)(IN_F - 1));
        Cs[k][t & 255] = __cosf(fmaf(c, cf[k], cp[k]));
    }
    __syncthreads();

    // std = sqrt(2/(in+out)) = sqrt(1/4096) = 1/64 exactly
    const float as = (1.0f / (1.0f + __expf(-alpha[0]))) * 0.015625f;
    const float bs = (1.0f / (1.0f + __expf(-beta[0])))  * 0.015625f;

    for (int g = tid; g < 128 * 64; g += 256) {
        const int r  = g >> 6;
        const int cg = g & 63;
        const int o  = o0 + r;
        const int i  = i0 + cg * 4;
        float4 acc = make_float4(0.f, 0.f, 0.f, 0.f);
        #pragma unroll
        for (int k = 0; k < NF; ++k) {
            float s = Ss[k][r];
            float4 c4 = *(const float4*)&Cs[k][cg * 4];
            acc.x = fmaf(s, c4.x, acc.x);
            acc.y = fmaf(s, c4.y, acc.y);
            acc.z = fmaf(s, c4.z, acc.z);
            acc.w = fmaf(s, c4.w, acc.w);
        }
        const float a0 = lora_A[o * 2 + 0], a1 = lora_A[o * 2 + 1];
        const float4 B0 = ((const float4*)lora_B)[i >> 2];
        const float4 B1 = ((const float4*)(lora_B + IN_F))[i >> 2];
        // tanh(W_lora) == W_lora to ~1e-12 abs (entries ~1e-4): linearized.
        float w0 = fmaf(as, tanh_fast(acc.x), bs * fmaf(a0, B0.x, a1 * B1.x));
        float w1 = fmaf(as, tanh_fast(acc.y), bs * fmaf(a0, B0.y, a1 * B1.y));
        float w2 = fmaf(as, tanh_fast(acc.z), bs * fmaf(a0, B0.z, a1 * B1.z));
        float w3 = fmaf(as, tanh_fast(acc.w), bs * fmaf(a0, B0.w, a1 * B1.w));
        __half2 h0 = __floats2half2_rn(w0, w1);
        __half2 h1 = __floats2half2_rn(w2, w3);
        size_t off = (size_t)o * IN_F + i;
        *(uint2*)(g_Wf + off) = make_uint2(*(uint32_t*)&h0, *(uint32_t*)&h1);
    }
}

// ---------------- kernel 3: mma.sync fp16 GEMM  out = x @ W^T + bias ----------------
// (byte-identical mainloop to R13: 128 threads, 2x2 warps, 64x64 warp tile,
// fragments prefetched one ks-step ahead incl. across chunk boundaries,
// ONE barrier per iteration.)
// smem stage layout: [x 16K][W 16K]; rows are 128B, SW128 swizzled.
DI void stage_fill(uint32_t sbase, const __half* gx, const __half* gw, uint32_t s0) {
    #pragma unroll
    for (int r = 0; r < 8; ++r) {
        cp16(sbase + s0 + r * 2048,         gx + (size_t)(r * 16) * IN_F);
        cp16(sbase + s0 + r * 2048 + TILEB, gw + (size_t)(r * 16) * IN_F);
    }
}

__global__ void __launch_bounds__(128, 2) k_gemm(const float* __restrict__ bias,
                                                 float* __restrict__ out) {
    extern __shared__ char smem[];
    const uint32_t sb = smem_to_u32(smem);
    const int tid  = threadIdx.x;
    const int wid  = tid >> 5;
    const int lane = tid & 31;
    const int n0 = blockIdx.x * BN;
    const int m0 = blockIdx.y * BM;
    const int wm = wid & 1;                 // 0..1 -> 64-row slab of x
    const int wn = wid >> 1;                // 0..1 -> 64-col slab of W

    float acc[4][8][4];
    #pragma unroll
    for (int i = 0; i < 4; ++i)
        #pragma unroll
        for (int j = 0; j < 8; ++j)
            #pragma unroll
            for (int q = 0; q < 4; ++q) acc[i][j][q] = 0.f;

    // persistent global pointers for the fill path
    const __half* gx = g_xf + (size_t)(m0 + (tid >> 3)) * IN_F + (tid & 7) * 8;
    const __half* gw = g_Wf + (size_t)(n0 + (tid >> 3)) * IN_F + (tid & 7) * 8;
    const uint32_t s0 = sw128((uint32_t)((tid >> 3) * 128 + (tid & 7) * 16));

    // precomputed ldmatrix smem offsets (stage-relative)
    uint32_t aoff[4], boff[4];
    {
        const int arow_l = (lane & 15);
        const int akb    = (lane >> 4) * 16;
        #pragma unroll
        for (int mi = 0; mi < 4; ++mi) {
            const int row = wm * 64 + mi * 16 + arow_l;
            aoff[mi] = sw128((uint32_t)(row * 128 + akb));
        }
        const int brow_l = (lane & 7) + ((lane >> 4) << 3);
        const int bkb    = ((lane >> 3) & 1) * 16;
        #pragma unroll
        for (int pi = 0; pi < 4; ++pi) {
            const int row = wn * 64 + pi * 16 + brow_l;
            boff[pi] = sw128((uint32_t)(row * 128 + bkb));
        }
    }

    // prologue: 2 stages in flight
    stage_fill(sb + 0 * STAGEB, gx, gw, s0);
    CP_COMMIT();
    gx += BK; gw += BK;
    stage_fill(sb + 1 * STAGEB, gx, gw, s0);
    CP_COMMIT();
    gx += BK; gw += BK;

    uint32_t st = sb;                        // compute stage base (cycles over 3)
    uint32_t fs = sb + 2 * STAGEB;           // fill stage base (cycles over 3)
    const uint32_t send = sb + 3 * STAGEB;

    uint32_t ah[2][4][4], bh[2][8][2];       // double-buffered fragments

    // make stage0 visible, preload its ks=0 fragments into buffer 0
    CP_WAIT1();
    __syncthreads();
    #pragma unroll
    for (int mi = 0; mi < 4; ++mi)
        ldsm4(ah[0][mi], st + aoff[mi]);
    #pragma unroll
    for (int pi = 0; pi < 4; ++pi)
        ldsm4(&bh[0][2 * pi][0], st + TILEB + boff[pi]);

    for (int it = 0; it < KCHUNKS; ++it) {
        // fill stage it+2 into slot (it+2)%3 == (it-1)%3 — safe: all reads of
        // that slot finished before the barrier of iteration it-1
        if (it + 2 < KCHUNKS) {
            stage_fill(fs, gx, gw, s0);
            gx += BK; gw += BK;
            fs += STAGEB; if (fs == send) fs = sb;
        }
        CP_COMMIT();

        // ks = 0..2: prefetch ks+1 (same stage), mma current
        #pragma unroll
        for (int ks = 0; ks < 3; ++ks) {
            const int cur = ks & 1, nxt = cur ^ 1;
            const uint32_t kb = (uint32_t)((ks + 1) * 32);   // kb<128: sw128(kb)==kb
            #pragma unroll
            for (int mi = 0; mi < 4; ++mi)
                ldsm4(ah[nxt][mi], st + (aoff[mi] ^ kb));
            #pragma unroll
            for (int pi = 0; pi < 4; ++pi)
                ldsm4(&bh[nxt][2 * pi][0], st + TILEB + (boff[pi] ^ kb));
            #pragma unroll
            for (int mi = 0; mi < 4; ++mi)
                #pragma unroll
                for (int ni = 0; ni < 8; ++ni)
                    mma_fp16(acc[mi][ni], ah[cur][mi], bh[cur][ni]);
        }

        CP_WAIT1();                           // retires fill of stage it+1
        __syncthreads();                      // stage it+1 visible; all reads of stage it done

        // ks = 3: prefetch ks0 of the NEXT stage into buf0, mma buf1
        {
            const uint32_t stn = (st + STAGEB == send) ? sb : st + STAGEB;
            #pragma unroll
            for (int mi = 0; mi < 4; ++mi)
                ldsm4(ah[0][mi], stn + aoff[mi]);
            #pragma unroll
            for (int pi = 0; pi < 4; ++pi)
                ldsm4(&bh[0][2 * pi][0], stn + TILEB + boff[pi]);
            #pragma unroll
            for (int mi = 0; mi < 4; ++mi)
                #pragma unroll
                for (int ni = 0; ni < 8; ++ni)
                    mma_fp16(acc[mi][ni], ah[1][mi], bh[1][ni]);
            st = stn;
        }
    }

    // epilogue: acc -> out (+bias)
    const int gid = lane >> 2, tig = lane & 3;
    const int mbase = m0 + wm * 64;
    const int nbase = n0 + wn * 64;
    #pragma unroll
    for (int ni = 0; ni < 8; ++ni) {
        const int n = nbase + ni * 8 + 2 * tig;
        const float2 bv = *(const float2*)(bias + n);
        #pragma unroll
        for (int mi = 0; mi < 4; ++mi) {
            const int m = mbase + mi * 16 + gid;
            float2 v0, v1;
            v0.x = acc[mi][ni][0] + bv.x;  v0.y = acc[mi][ni][1] + bv.y;
            v1.x = acc[mi][ni][2] + bv.x;  v1.y = acc[mi][ni][3] + bv.y;
            *(float2*)(out + (size_t)m * OUT_F + n)       = v0;
            *(float2*)(out + (size_t)(m + 8) * OUT_F + n) = v1;
        }
    }
}

// ---------------- launch ----------------
extern "C" void kernel_launch(void* const* d_in, const int* in_sizes, int n_in,
                              void* d_out, int out_size) {
    const float* x      = (const float*)d_in[0];
    const float* amp    = (const float*)d_in[1];
    const float* rf     = (const float*)d_in[2];
    const float* cf     = (const float*)d_in[3];
    const float* rp     = (const float*)d_in[4];
    const float* cp     = (const float*)d_in[5];
    const float* lora_A = (const float*)d_in[6];
    const float* lora_B = (const float*)d_in[7];
    const float* alpha  = (const float*)d_in[8];
    const float* beta   = (const float*)d_in[9];
    const float* bias   = (const float*)d_in[10];
    float* out = (float*)d_out;

    cudaFuncSetAttribute(k_gemm, cudaFuncAttributeMaxDynamicSharedMemorySize, SMEM_BYTES);

    k_cvt_x<<<((size_t)N_TOK * IN_F / 8) / 256, 256>>>((const float4*)x);
    k_build_w<<<dim3(IN_F / 256, OUT_F / 128), 256>>>(amp, rf, cf, rp, cp,
                                                      lora_A, lora_B, alpha, beta);
    k_gemm<<<dim3(OUT_F / BN, N_TOK / BM), 128, SMEM_BYTES>>>(bias, out);
}